// round 10
// baseline (speedup 1.0000x reference)
#include <cuda_runtime.h>
#include <cstdint>

// BinCat: idx = sum_j (1 - x[b,i,j]) * 2^(19-j), out[row,:] = cats[idx,:]
// x:    (4096, 16, 20) int32 (0/1) ; cats: (2^20, 64) f32 ; out: (B*I, 64) f32
//
// R10: idx-SORTED gather. Evidence: every prior structure caps at ~2.4TB/s
// DRAM with no pipe saturated => DRAM drain-rate bound on random 256B row
// activations. Reads are demand (order matters); writes are fire-and-forget
// and the whole 16.8MB output fits in L2 (126MB) => scatter the writes,
// sort the reads. 64K-bin counting sort (bin = idx>>4, ~1 item/bin).
//
// Kernels: A idx+hist -> B1 intra-block scan -> B2 block-offset add ->
//          C scatter (row,idx) into sorted order -> D sorted gather
//          (D also re-zeros the histogram for the next graph replay).

static constexpr int LENGTH   = 20;
static constexpr int DIM      = 64;
static constexpr int MAX_ROWS = 4096 * 16;   // 65536
static constexpr int BINS     = 1 << 16;     // idx >> 4
static constexpr int SCAN_BLOCKS = 64;       // 64 CTAs x 1024 bins

__device__ unsigned g_hist[BINS];            // zero at load; D re-zeros each run
__device__ unsigned g_blocksum[SCAN_BLOCKS];
__device__ unsigned g_idx[MAX_ROWS];
__device__ uint2    g_sorted[MAX_ROWS];      // {row, idx}

// ---------- A: per-row index + histogram ----------
__global__ void __launch_bounds__(256)
k_index_hist(const int* __restrict__ x, int nrows)
{
    const int row = blockIdx.x * 256 + threadIdx.x;
    if (row >= nrows) return;

    const int4* __restrict__ xr =
        reinterpret_cast<const int4*>(x + (size_t)row * LENGTH);
    const int4 a0 = __ldg(&xr[0]);
    const int4 a1 = __ldg(&xr[1]);
    const int4 a2 = __ldg(&xr[2]);
    const int4 a3 = __ldg(&xr[3]);
    const int4 a4 = __ldg(&xr[4]);
    const int v[LENGTH] = { a0.x, a0.y, a0.z, a0.w,
                            a1.x, a1.y, a1.z, a1.w,
                            a2.x, a2.y, a2.z, a2.w,
                            a3.x, a3.y, a3.z, a3.w,
                            a4.x, a4.y, a4.z, a4.w };
    unsigned idx = 0u;
    #pragma unroll
    for (int j = 0; j < LENGTH; ++j)
        idx |= (unsigned)(1 - v[j]) << (LENGTH - 1 - j);

    g_idx[row] = idx;
    atomicAdd(&g_hist[idx >> 4], 1u);
}

// ---------- B1: exclusive scan within each 1024-bin block ----------
__global__ void __launch_bounds__(256)
k_scan1()
{
    __shared__ unsigned ssum[256];
    const int b = blockIdx.x, t = threadIdx.x;
    const unsigned base = (unsigned)b * 1024u + (unsigned)t * 4u;

    uint4 c = *reinterpret_cast<uint4*>(&g_hist[base]);
    const unsigned tot = c.x + c.y + c.z + c.w;
    ssum[t] = tot;
    __syncthreads();

    // Hillis-Steele inclusive scan over 256 thread totals
    for (int o = 1; o < 256; o <<= 1) {
        unsigned u = (t >= o) ? ssum[t - o] : 0u;
        __syncthreads();
        ssum[t] += u;
        __syncthreads();
    }
    const unsigned excl = ssum[t] - tot;

    uint4 o4;
    o4.x = excl;
    o4.y = excl + c.x;
    o4.z = excl + c.x + c.y;
    o4.w = excl + c.x + c.y + c.z;
    *reinterpret_cast<uint4*>(&g_hist[base]) = o4;

    if (t == 255) g_blocksum[b] = ssum[255];     // block total
}

// ---------- B2: add cross-block prefix ----------
__global__ void __launch_bounds__(256)
k_scan2()
{
    __shared__ unsigned off;
    const int b = blockIdx.x, t = threadIdx.x;
    if (t == 0) {
        unsigned s = 0;
        for (int i = 0; i < b; ++i) s += g_blocksum[i];
        off = s;
    }
    __syncthreads();
    const unsigned o = off;
    const unsigned base = (unsigned)b * 1024u + (unsigned)t * 4u;
    uint4 c = *reinterpret_cast<uint4*>(&g_hist[base]);
    c.x += o; c.y += o; c.z += o; c.w += o;
    *reinterpret_cast<uint4*>(&g_hist[base]) = c;
}

// ---------- C: scatter (row, idx) into sorted positions ----------
__global__ void __launch_bounds__(256)
k_scatter(int nrows)
{
    const int row = blockIdx.x * 256 + threadIdx.x;
    if (row >= nrows) return;
    const unsigned idx = g_idx[row];
    const unsigned pos = atomicAdd(&g_hist[idx >> 4], 1u);
    g_sorted[pos] = make_uint2((unsigned)row, idx);
}

// ---------- D: sorted gather (reads sequential-ish, writes L2-absorbed) ----------
static constexpr int ROWS_PER_WARP = 8;

__global__ void __launch_bounds__(256)
k_gather(const float* __restrict__ cats,
         float* __restrict__ out,
         int nrows)
{
    const int gtid = blockIdx.x * 256 + threadIdx.x;

    // re-zero histogram for the next graph replay (grid covers BINS)
    if (gtid < BINS) g_hist[gtid] = 0u;

    const int warp = gtid >> 5;
    const int lane = threadIdx.x & 31;
    const int base = warp * ROWS_PER_WARP;
    if (base >= nrows) return;

    uint2 pr = make_uint2(0u, 0u);
    if (lane < ROWS_PER_WARP && base + lane < nrows)
        pr = g_sorted[base + lane];              // coalesced 64B read

    unsigned rrow[ROWS_PER_WARP];
    float2   v[ROWS_PER_WARP];
    #pragma unroll
    for (int i = 0; i < ROWS_PER_WARP; ++i) {
        const unsigned ridx = __shfl_sync(0xffffffffu, pr.y, i);
        rrow[i]             = __shfl_sync(0xffffffffu, pr.x, i);
        const float2* __restrict__ src =
            reinterpret_cast<const float2*>(cats + (size_t)ridx * DIM);
        v[i] = __ldg(&src[lane]);                // idx-sorted -> row-buffer friendly
    }
    #pragma unroll
    for (int i = 0; i < ROWS_PER_WARP; ++i) {
        if (base + i < nrows) {
            float2* __restrict__ dst =
                reinterpret_cast<float2*>(out + (size_t)rrow[i] * DIM);
            dst[lane] = v[i];                    // scattered, absorbed by L2
        }
    }
}

extern "C" void kernel_launch(void* const* d_in, const int* in_sizes, int n_in,
                              void* d_out, int out_size)
{
    const int*   x    = (const int*)d_in[0];    // (B, I, 20) int32
    const float* cats = (const float*)d_in[1];  // (2^20, 64) float32
    float*       out  = (float*)d_out;          // (B, I, 64) float32

    int nrows = in_sizes[0] / LENGTH;           // 65536
    if (nrows > MAX_ROWS) nrows = MAX_ROWS;

    const int tpb = 256;
    const int blocksA = (nrows + tpb - 1) / tpb;                      // 256
    k_index_hist<<<blocksA, tpb>>>(x, nrows);
    k_scan1<<<SCAN_BLOCKS, tpb>>>();
    k_scan2<<<SCAN_BLOCKS, tpb>>>();
    k_scatter<<<blocksA, tpb>>>(nrows);

    const int rows_per_block = (tpb / 32) * ROWS_PER_WARP;            // 64
    const int blocksD = (nrows + rows_per_block - 1) / rows_per_block; // 1024
    k_gather<<<blocksD, tpb>>>(cats, out, nrows);
}

// round 13
// speedup vs baseline: 2.6295x; 2.6295x over previous
#include <cuda_runtime.h>
#include <cstdint>

// BinCat: idx = sum_j (1 - x[b,i,j]) * 2^(19-j), out[row,:] = cats[idx,:]
// x:    (4096, 16, 20) int32 (0/1)   -> 65536 rows of 80 B (16B-aligned)
// cats: (2^20, 64) float32           -> 256 B rows (256B-aligned)
// out:  (4096, 16, 64) float32
//
// R13 = R4 structure + 256-bit lanes + L2 evict_last (legal encoding).
//   sm_103a ptxas: .L2::evict_last requires .v8.b32/.v4.b64 (LDG.256).
//   So each lane moves 32 B: a warp covers 4 rows per instruction,
//   8 rows in 2 LDG.256s (vs 8 LDG.64s in R4) — fewer wavefronts, and the
//   evict_last hint tries to pin the ~15.7MB unique gather working set in
//   L2 across graph replays (identical replay -> same rows every time).
//   Stores: st.global.cs.v4.b64 (evict-first write-once stream).

static constexpr int LENGTH        = 20;
static constexpr int DIM           = 64;   // 256 B per row
static constexpr int ROWS_PER_WARP = 8;

__device__ __forceinline__ void ldg_el_256(const void* p,
                                           unsigned long long r[4])
{
    asm volatile("ld.global.nc.L2::evict_last.v4.b64 {%0,%1,%2,%3}, [%4];"
                 : "=l"(r[0]), "=l"(r[1]), "=l"(r[2]), "=l"(r[3])
                 : "l"(p));
}

__device__ __forceinline__ void stg_cs_256(void* p,
                                           const unsigned long long r[4])
{
    asm volatile("st.global.cs.v4.b64 [%0], {%1,%2,%3,%4};"
                 :: "l"(p), "l"(r[0]), "l"(r[1]), "l"(r[2]), "l"(r[3])
                 : "memory");
}

__global__ void __launch_bounds__(256)
bincat_gather_kernel(const int* __restrict__ x,
                     const float* __restrict__ cats,
                     float* __restrict__ out,
                     int nrows)
{
    const int gtid     = blockIdx.x * blockDim.x + threadIdx.x;
    const int warp_id  = gtid >> 5;
    const int lane     = threadIdx.x & 31;
    const int row_base = warp_id * ROWS_PER_WARP;
    if (row_base >= nrows) return;

    // ---- Phase 1: lanes 0..7 compute indices (rows are 80 B = 5 x int4) ----
    unsigned idx = 0u;
    if (lane < ROWS_PER_WARP) {
        const int myrow = row_base + lane;
        if (myrow < nrows) {
            const int4* __restrict__ xr =
                reinterpret_cast<const int4*>(x + (size_t)myrow * LENGTH);
            const int4 a0 = __ldcs(&xr[0]);
            const int4 a1 = __ldcs(&xr[1]);
            const int4 a2 = __ldcs(&xr[2]);
            const int4 a3 = __ldcs(&xr[3]);
            const int4 a4 = __ldcs(&xr[4]);
            const int v[LENGTH] = { a0.x, a0.y, a0.z, a0.w,
                                    a1.x, a1.y, a1.z, a1.w,
                                    a2.x, a2.y, a2.z, a2.w,
                                    a3.x, a3.y, a3.z, a3.w,
                                    a4.x, a4.y, a4.z, a4.w };
            #pragma unroll
            for (int j = 0; j < LENGTH; ++j)
                idx |= (unsigned)(1 - v[j]) << (LENGTH - 1 - j);
        }
    }

    // ---- Phase 2: 256-bit cooperative gather ----
    // Lane l handles row (row_base + 4*g + (l>>3)), byte chunk (l&7)*32.
    const int sub   = lane >> 3;        // 0..3: row within group of 4
    const int chunk = lane & 7;         // 0..7: 32B chunk within 256B row

    unsigned long long v0[4], v1[4];
    int r0, r1;
    {   // group 0: rows row_base + 0..3
        const unsigned ridx = __shfl_sync(0xffffffffu, idx, sub);
        r0 = row_base + sub;
        const char* src = reinterpret_cast<const char*>(cats)
                        + ((size_t)ridx * 256u) + (size_t)chunk * 32u;
        ldg_el_256(src, v0);
    }
    {   // group 1: rows row_base + 4..7
        const unsigned ridx = __shfl_sync(0xffffffffu, idx, 4 + sub);
        r1 = row_base + 4 + sub;
        const char* src = reinterpret_cast<const char*>(cats)
                        + ((size_t)ridx * 256u) + (size_t)chunk * 32u;
        ldg_el_256(src, v1);
    }

    // ---- stores: evict-first 256-bit, fully coalesced ----
    if (r0 < nrows) {
        char* dst = reinterpret_cast<char*>(out)
                  + (size_t)r0 * 256u + (size_t)chunk * 32u;
        stg_cs_256(dst, v0);
    }
    if (r1 < nrows) {
        char* dst = reinterpret_cast<char*>(out)
                  + (size_t)r1 * 256u + (size_t)chunk * 32u;
        stg_cs_256(dst, v1);
    }
}

extern "C" void kernel_launch(void* const* d_in, const int* in_sizes, int n_in,
                              void* d_out, int out_size)
{
    const int*   x    = (const int*)d_in[0];    // (B, I, 20) int32
    const float* cats = (const float*)d_in[1];  // (2^20, 64) float32
    float*       out  = (float*)d_out;          // (B, I, 64) float32

    const int nrows = in_sizes[0] / LENGTH;     // 65536

    const int threads = 256;                                   // 8 warps
    const int rows_per_block = (threads / 32) * ROWS_PER_WARP; // 64 rows
    const int blocks = (nrows + rows_per_block - 1) / rows_per_block; // 1024

    bincat_gather_kernel<<<blocks, threads>>>(x, cats, out, nrows);
}